// round 2
// baseline (speedup 1.0000x reference)
#include <cuda_runtime.h>
#include <math.h>

#define Bq   4
#define Nq   65536
#define Gq   64
#define G3q  262144          // 64^3
#define CF   32
#define HW   128
#define VSC  0.05f
#define R2C  1.5625f         // 1.25^2

typedef unsigned long long ull;

// -------- device scratch (no allocations allowed) --------
__device__ float         g_P[(size_t)Bq * HW * HW * 64];   // 16 MB projected feature map
__device__ unsigned char g_occS[(size_t)Bq * G3q];         // occupancy (nearby-gated)
__device__ unsigned char g_occA[(size_t)Bq * G3q];         // occupancy (bounds only)
__device__ int           g_anyNearby[Bq];
__device__ int           g_anyOccS[Bq];
__device__ int           g_anyOccA[Bq];
__device__ float         g_accum[Bq][8];                   // w, w*px, w*py, w*pz, px, py, pz

// -------- packed f32x2 helpers (Blackwell FFMA2 path) --------
__device__ __forceinline__ ull ffma2(ull a, ull b, ull c) {
    ull d; asm("fma.rn.f32x2 %0,%1,%2,%3;" : "=l"(d) : "l"(a), "l"(b), "l"(c)); return d;
}
__device__ __forceinline__ ull add2(ull a, ull b) {
    ull d; asm("add.rn.f32x2 %0,%1,%2;" : "=l"(d) : "l"(a), "l"(b)); return d;
}
__device__ __forceinline__ ull pack2(float lo, float hi) {
    ull d; asm("mov.b64 %0,{%1,%2};" : "=l"(d) : "f"(lo), "f"(hi)); return d;
}
__device__ __forceinline__ void unpack2(ull v, float& lo, float& hi) {
    asm("mov.b64 {%0,%1},%2;" : "=f"(lo), "=f"(hi) : "l"(v));
}

// ---------------------------------------------------------
__global__ void k_clear() {
    int i = blockIdx.x * blockDim.x + threadIdx.x;   // 0 .. 262143
    ((int*)g_occS)[i] = 0;           // Bq*G3q bytes == G3q ints
    ((int*)g_occA)[i] = 0;
    if (i < Bq) { g_anyNearby[i] = 0; g_anyOccS[i] = 0; g_anyOccA[i] = 0; }
    if (i < Bq * 8) ((float*)g_accum)[i] = 0.0f;
}

__device__ __forceinline__ bool is_nearby(float px, float py, float pz,
                                          float ax, float ay, float az) {
    float dx = px - ax, dy = py - ay;
    float d2xy = dx * dx + dy * dy;
    float e0 = pz - (az - 0.5f);
    float e1 = pz - az;
    float e2 = pz - (az + 0.5f);
    float m = fminf(fminf(e0 * e0, e1 * e1), e2 * e2);
    return (d2xy + m) <= R2C;
}

// single fused pass: scatter both occupancy grids + flags (4 points/thread)
__global__ void __launch_bounds__(256) k_scatter(const float* __restrict__ points,
                                                 const float* __restrict__ pelvis) {
    int idx4 = blockIdx.x * 256 + threadIdx.x;      // B*N/4 groups
    int b = idx4 >> 14;                             // 16384 groups per batch
    float ax = pelvis[b * 3 + 0], ay = pelvis[b * 3 + 1], az = pelvis[b * 3 + 2];
    int v0x = (int)floorf(ax / VSC) - (Gq / 2);
    int v0y = (int)floorf(ay / VSC) - (Gq / 2);
    int v0z = (int)floorf(az / VSC) - (Gq / 2);

    const float4* pp = (const float4*)(points + (size_t)idx4 * 12);
    float4 A = pp[0], Bv = pp[1], C = pp[2];
    float P[4][3] = { {A.x, A.y, A.z}, {A.w, Bv.x, Bv.y},
                      {Bv.z, Bv.w, C.x}, {C.y, C.z, C.w} };

    bool anyNb = false, anyS = false, anyA = false;
#pragma unroll
    for (int k = 0; k < 4; ++k) {
        float px = P[k][0], py = P[k][1], pz = P[k][2];
        bool nb = is_nearby(px, py, pz, ax, ay, az);
        int lx = (int)floorf(px / VSC) - v0x;
        int ly = (int)floorf(py / VSC) - v0y;
        int lz = (int)floorf(pz / VSC) - v0z;
        bool bounds = (unsigned)lx < (unsigned)Gq && (unsigned)ly < (unsigned)Gq
                    && (unsigned)lz < (unsigned)Gq;
        int cell = (lx << 12) + (ly << 6) + lz;
        if (bounds) {
            g_occA[(size_t)b * G3q + cell] = 1;
            if (nb) g_occS[(size_t)b * G3q + cell] = 1;
        }
        anyNb |= nb; anyS |= (nb && bounds); anyA |= bounds;
    }
    unsigned mN = __ballot_sync(0xffffffffu, anyNb);
    unsigned mS = __ballot_sync(0xffffffffu, anyS);
    unsigned mA = __ballot_sync(0xffffffffu, anyA);
    if ((threadIdx.x & 31) == 0) {
        if (mN) atomicOr(&g_anyNearby[b], 1);
        if (mS) atomicOr(&g_anyOccS[b], 1);
        if (mA) atomicOr(&g_anyOccA[b], 1);
    }
}

// Precompute P[b,y,x,j] = sum_c fmap[b,c,y,x] * W1[3+c, j]
__global__ void __launch_bounds__(256) k_proj(const float* __restrict__ fmap,
                                              const float* __restrict__ W1) {
    int idx = blockIdx.x * 256 + threadIdx.x;   // B*HW*HW*64 threads
    int j   = idx & 63;
    int rest = idx >> 6;
    int pix = rest & (HW * HW - 1);
    int b   = rest >> 14;
    const float* fp = fmap + (size_t)b * CF * HW * HW + pix;
    float a = 0.0f;
#pragma unroll
    for (int c = 0; c < CF; ++c)
        a = fmaf(__ldg(fp + c * HW * HW), W1[(3 + c) * 64 + j], a);
    g_P[(size_t)idx] = a;
}

// ---------------------------------------------------------
// Main kernel: warp = 8 voxels x 4 lanes. Lane (v,q): voxel v, channel chunk q.
// Coalesced 64B-per-voxel tap loads, packed f32x2 MLP, 4-lane bfly reduce.
__global__ void __launch_bounds__(256) k_main(const float* __restrict__ pelvis,
                                              const float* __restrict__ Kmat,
                                              const float* __restrict__ bbx,
                                              const float* __restrict__ W1,
                                              const float* __restrict__ b1,
                                              const float* __restrict__ W2,
                                              const float* __restrict__ b2,
                                              float* __restrict__ outp) {
    __shared__ ull  sW1x[32], sW1y[32], sW1z[32], sB1[32];   // packed channel pairs
    __shared__ ull  sW2[64 * 6];                             // row j: 6 packed output pairs
    __shared__ float sB2[12];
    __shared__ float sred[8][7];

    int t = threadIdx.x;
    if (t < 32) {
        sW1x[t] = pack2(W1[2 * t],       W1[2 * t + 1]);
        sW1y[t] = pack2(W1[64 + 2 * t],  W1[64 + 2 * t + 1]);
        sW1z[t] = pack2(W1[128 + 2 * t], W1[128 + 2 * t + 1]);
        sB1[t]  = pack2(b1[2 * t],       b1[2 * t + 1]);
    }
    for (int i = t; i < 384; i += 256) {
        int j = i / 6, r = i % 6;
        sW2[i] = pack2(W2[j * 12 + 2 * r], W2[j * 12 + 2 * r + 1]);
    }
    if (t < 12) sB2[t] = b2[t];
    __syncthreads();

    int b    = blockIdx.y;
    int warp = t >> 5, lane = t & 31;
    int v    = lane >> 2, q = lane & 3;
    int g    = blockIdx.x * 64 + warp * 8 + v;

    float ax = pelvis[b * 3 + 0], ay = pelvis[b * 3 + 1], az = pelvis[b * 3 + 2];
    int anyNb = g_anyNearby[b];
    int v0x = (int)floorf(ax / VSC) - (Gq / 2);
    int v0y = (int)floorf(ay / VSC) - (Gq / 2);
    int v0z = (int)floorf(az / VSC) - (Gq / 2);

    int gx = g >> 12, gy = (g >> 6) & 63, gz = g & 63;
    float cxv = (float)(v0x + gx) * VSC + VSC * 0.5f;
    float cyv = (float)(v0y + gy) * VSC + VSC * 0.5f;
    float czv = (float)(v0z + gz) * VSC + VSC * 0.5f;

    float fx = Kmat[b * 9 + 0], cx0 = Kmat[b * 9 + 2];
    float fy = Kmat[b * 9 + 4], cy0 = Kmat[b * 9 + 5];
    float l = bbx[b * 4 + 0], tp = bbx[b * 4 + 1];
    float r = bbx[b * 4 + 2], bt = bbx[b * 4 + 3];

    float u  = cxv / czv * fx + cx0;
    float vp = cyv / czv * fy + cy0;
    float U = (u - l) / (r - l) * (float)(HW - 1);
    float V = (vp - tp) / (bt - tp) * (float)(HW - 1);

    float x0f = floorf(U), y0f = floorf(V);
    float wx = U - x0f, wy = V - y0f;
    int x0 = (int)x0f, y0 = (int)y0f;
    int x1 = x0 + 1, y1 = y0 + 1;
    bool okx0 = (x0 >= 0 && x0 <= HW - 1), okx1 = (x1 >= 0 && x1 <= HW - 1);
    bool oky0 = (y0 >= 0 && y0 <= HW - 1), oky1 = (y1 >= 0 && y1 <= HW - 1);
    int x0c = min(max(x0, 0), HW - 1), x1c = min(max(x1, 0), HW - 1);
    int y0c = min(max(y0, 0), HW - 1), y1c = min(max(y1, 0), HW - 1);

    float w00 = (1.0f - wx) * (1.0f - wy) * ((okx0 && oky0) ? 1.0f : 0.0f);
    float w10 = wx * (1.0f - wy)          * ((okx1 && oky0) ? 1.0f : 0.0f);
    float w01 = (1.0f - wx) * wy          * ((okx0 && oky1) ? 1.0f : 0.0f);
    float w11 = wx * wy                   * ((okx1 && oky1) ? 1.0f : 0.0f);

    const float* Pb = g_P + (size_t)b * (HW * HW * 64);
    const ulonglong2* b00 = (const ulonglong2*)(Pb + ((y0c * HW + x0c) << 6));
    const ulonglong2* b10 = (const ulonglong2*)(Pb + ((y0c * HW + x1c) << 6));
    const ulonglong2* b01 = (const ulonglong2*)(Pb + ((y1c * HW + x0c) << 6));
    const ulonglong2* b11 = (const ulonglong2*)(Pb + ((y1c * HW + x1c) << 6));

    ull w00_2 = pack2(w00, w00), w10_2 = pack2(w10, w10);
    ull w01_2 = pack2(w01, w01), w11_2 = pack2(w11, w11);
    float geox = ax - cxv, geoy = ay - cyv, geoz = az - czv;
    ull gx2 = pack2(geox, geox), gy2 = pack2(geoy, geoy), gz2 = pack2(geoz, geoz);

    ull acc2[6] = {0ull, 0ull, 0ull, 0ull, 0ull, 0ull};

#pragma unroll
    for (int i = 0; i < 4; ++i) {
        int chunk = q + 4 * i;          // 16B chunk index within 256B pixel row
        int ch    = chunk * 4;          // first of 4 channels this iteration
        ulonglong2 t00 = b00[chunk], t10 = b10[chunk];
        ulonglong2 t01 = b01[chunk], t11 = b11[chunk];

        ull s0 = ffma2(w00_2, t00.x, ffma2(w10_2, t10.x,
                 ffma2(w01_2, t01.x, ffma2(w11_2, t11.x, 0ull))));
        ull s1 = ffma2(w00_2, t00.y, ffma2(w10_2, t10.y,
                 ffma2(w01_2, t01.y, ffma2(w11_2, t11.y, 0ull))));

        int p0 = chunk * 2;             // packed channel-pair indices
        ull h0p = ffma2(gx2, sW1x[p0],     ffma2(gy2, sW1y[p0],
                  ffma2(gz2, sW1z[p0],     add2(s0, sB1[p0]))));
        ull h1p = ffma2(gx2, sW1x[p0 + 1], ffma2(gy2, sW1y[p0 + 1],
                  ffma2(gz2, sW1z[p0 + 1], add2(s1, sB1[p0 + 1]))));

        float ha, hb, hc, hd;
        unpack2(h0p, ha, hb); unpack2(h1p, hc, hd);
        ha = fmaxf(ha, 0.0f); hb = fmaxf(hb, 0.0f);
        hc = fmaxf(hc, 0.0f); hd = fmaxf(hd, 0.0f);

        const ull* w2a = &sW2[(ch + 0) * 6];
        const ull* w2b = &sW2[(ch + 1) * 6];
        const ull* w2c = &sW2[(ch + 2) * 6];
        const ull* w2d = &sW2[(ch + 3) * 6];
        ull hha = pack2(ha, ha), hhb = pack2(hb, hb);
        ull hhc = pack2(hc, hc), hhd = pack2(hd, hd);
#pragma unroll
        for (int rr = 0; rr < 6; ++rr) {
            acc2[rr] = ffma2(hha, w2a[rr], acc2[rr]);
            acc2[rr] = ffma2(hhb, w2b[rr], acc2[rr]);
            acc2[rr] = ffma2(hhc, w2c[rr], acc2[rr]);
            acc2[rr] = ffma2(hhd, w2d[rr], acc2[rr]);
        }
    }

    // reduce over the 4 lanes of each voxel group (packed adds)
#pragma unroll
    for (int rr = 0; rr < 6; ++rr) {
        ull o = __shfl_xor_sync(0xffffffffu, acc2[rr], 1);
        acc2[rr] = add2(acc2[rr], o);
        o = __shfl_xor_sync(0xffffffffu, acc2[rr], 2);
        acc2[rr] = add2(acc2[rr], o);
    }
    float acc[12];
#pragma unroll
    for (int rr = 0; rr < 6; ++rr) {
        unpack2(acc2[rr], acc[2 * rr], acc[2 * rr + 1]);
        acc[2 * rr]     += sB2[2 * rr];
        acc[2 * rr + 1] += sB2[2 * rr + 1];
    }

    // write out[b, g, 0:12]: lanes q=0..2 each write one float4 chunk
    float* op = outp + ((size_t)b * G3q + g) * 12;
    if (q == 0)      *(float4*)(op + 0) = make_float4(acc[0], acc[1], acc[2], acc[3]);
    else if (q == 1) *(float4*)(op + 4) = make_float4(acc[4], acc[5], acc[6], acc[7]);
    else if (q == 2) *(float4*)(op + 8) = make_float4(acc[8], acc[9], acc[10], acc[11]);

    // softmax contributions (shift-free: s = sigmoid in (0,1), exp safe)
    float red7[7] = {0, 0, 0, 0, 0, 0, 0};
    if (q == 0) {
        size_t oidx = (size_t)b * G3q + g;
        unsigned char occv = anyNb ? g_occS[oidx] : g_occA[oidx];
        float sg  = 1.0f / (1.0f + expf(-acc[0]));
        float wgt = occv ? expf(sg) : 0.0f;
        float px = cxv + acc[1], py = cyv + acc[2], pz = czv + acc[3];
        red7[0] = wgt; red7[1] = wgt * px; red7[2] = wgt * py; red7[3] = wgt * pz;
        red7[4] = px;  red7[5] = py;       red7[6] = pz;
    }
#pragma unroll
    for (int i = 0; i < 7; ++i) {
        float vv = red7[i];
        vv += __shfl_xor_sync(0xffffffffu, vv, 16);
        vv += __shfl_xor_sync(0xffffffffu, vv, 8);
        vv += __shfl_xor_sync(0xffffffffu, vv, 4);
        vv += __shfl_xor_sync(0xffffffffu, vv, 2);
        vv += __shfl_xor_sync(0xffffffffu, vv, 1);
        red7[i] = vv;
    }
    if (lane == 0) {
#pragma unroll
        for (int i = 0; i < 7; ++i) sred[warp][i] = red7[i];
    }
    __syncthreads();
    if (t < 7) {
        float s = 0.0f;
#pragma unroll
        for (int w = 0; w < 8; ++w) s += sred[w][t];
        atomicAdd(&g_accum[b][t], s);
    }
}

__global__ void k_finalize(const float* __restrict__ pelvis,
                           float* __restrict__ refined) {
    int b = threadIdx.x;
    if (b >= Bq) return;
    int anyOcc = g_anyNearby[b] ? g_anyOccS[b] : g_anyOccA[b];
    float wsum = g_accum[b][0];
    float x, y, z;
    if (anyOcc) {
        x = g_accum[b][1] / wsum;
        y = g_accum[b][2] / wsum;
        z = g_accum[b][3] / wsum;
    } else {                      // uniform softmax over all voxels
        x = g_accum[b][4] / (float)G3q;
        y = g_accum[b][5] / (float)G3q;
        z = g_accum[b][6] / (float)G3q;
    }
    bool bad = isnan(x) || isnan(y) || isnan(z);
    refined[b * 3 + 0] = bad ? pelvis[b * 3 + 0] : x;
    refined[b * 3 + 1] = bad ? pelvis[b * 3 + 1] : y;
    refined[b * 3 + 2] = bad ? pelvis[b * 3 + 2] : z;
}

extern "C" void kernel_launch(void* const* d_in, const int* in_sizes, int n_in,
                              void* d_out, int out_size) {
    const float* points = (const float*)d_in[0];
    const float* fmap   = (const float*)d_in[1];
    const float* pelvis = (const float*)d_in[2];
    const float* Kmat   = (const float*)d_in[3];
    const float* bbx    = (const float*)d_in[4];
    const float* W1     = (const float*)d_in[5];
    const float* b1     = (const float*)d_in[6];
    const float* W2     = (const float*)d_in[7];
    const float* b2     = (const float*)d_in[8];

    float* refined = (float*)d_out;          // (B,3) first
    float* outp    = (float*)d_out + Bq * 3; // (B,G3,12) second

    k_clear<<<G3q / 256, 256>>>();
    k_proj<<<(Bq * HW * HW * 64) / 256, 256>>>(fmap, W1);
    k_scatter<<<(Bq * Nq / 4) / 256, 256>>>(points, pelvis);
    k_main<<<dim3(G3q / 64, Bq), 256>>>(pelvis, Kmat, bbx, W1, b1, W2, b2, outp);
    k_finalize<<<1, 32>>>(pelvis, refined);
}

// round 5
// speedup vs baseline: 1.7206x; 1.7206x over previous
#include <cuda_runtime.h>
#include <math.h>

#define Bq   4
#define Nq   65536
#define Gq   64
#define G3q  262144          // 64^3
#define CF   32
#define HW   128
#define NPIX (HW * HW)       // 16384
#define VSC  0.05f
#define R2C  1.5625f         // 1.25^2

typedef unsigned long long ull;

// -------- device scratch (no allocations allowed) --------
// P stored as 16 channel-chunk planes per batch: g_P4[((b*16 + c4) << 14) + pix] = float4
__device__ float4        g_P4[(size_t)Bq * 16 * NPIX];     // 16 MB projected feature map
__device__ unsigned char g_occS[(size_t)Bq * G3q];         // occupancy (nearby-gated)
__device__ unsigned char g_occA[(size_t)Bq * G3q];         // occupancy (bounds only)
__device__ int           g_anyNearby[Bq];
__device__ int           g_anyOccS[Bq];
__device__ int           g_anyOccA[Bq];
__device__ float         g_accum[Bq][8];

// -------- packed f32x2 helpers --------
__device__ __forceinline__ ull ffma2(ull a, ull b, ull c) {
    ull d; asm("fma.rn.f32x2 %0,%1,%2,%3;" : "=l"(d) : "l"(a), "l"(b), "l"(c)); return d;
}
__device__ __forceinline__ ull add2(ull a, ull b) {
    ull d; asm("add.rn.f32x2 %0,%1,%2;" : "=l"(d) : "l"(a), "l"(b)); return d;
}
__device__ __forceinline__ ull pack2(float lo, float hi) {
    ull d; asm("mov.b64 %0,{%1,%2};" : "=l"(d) : "f"(lo), "f"(hi)); return d;
}
__device__ __forceinline__ void unpack2(ull v, float& lo, float& hi) {
    asm("mov.b64 {%0,%1},%2;" : "=f"(lo), "=f"(hi) : "l"(v));
}

// ---------------------------------------------------------
__global__ void k_clear() {
    int i = blockIdx.x * blockDim.x + threadIdx.x;   // 0 .. 262143
    ((int*)g_occS)[i] = 0;
    ((int*)g_occA)[i] = 0;
    if (i < Bq) { g_anyNearby[i] = 0; g_anyOccS[i] = 0; g_anyOccA[i] = 0; }
    if (i < Bq * 8) ((float*)g_accum)[i] = 0.0f;
}

__device__ __forceinline__ bool is_nearby(float px, float py, float pz,
                                          float ax, float ay, float az) {
    float dx = px - ax, dy = py - ay;
    float d2xy = dx * dx + dy * dy;
    float e0 = pz - (az - 0.5f);
    float e1 = pz - az;
    float e2 = pz - (az + 0.5f);
    float m = fminf(fminf(e0 * e0, e1 * e1), e2 * e2);
    return (d2xy + m) <= R2C;
}

// fused scatter: both occupancy grids + flags (4 points/thread)
__global__ void __launch_bounds__(256) k_scatter(const float* __restrict__ points,
                                                 const float* __restrict__ pelvis) {
    int idx4 = blockIdx.x * 256 + threadIdx.x;      // B*N/4 groups
    int b = idx4 >> 14;
    float ax = pelvis[b * 3 + 0], ay = pelvis[b * 3 + 1], az = pelvis[b * 3 + 2];
    int v0x = (int)floorf(ax / VSC) - (Gq / 2);
    int v0y = (int)floorf(ay / VSC) - (Gq / 2);
    int v0z = (int)floorf(az / VSC) - (Gq / 2);

    const float4* pp = (const float4*)(points + (size_t)idx4 * 12);
    float4 A = pp[0], Bv = pp[1], C = pp[2];
    float P[4][3] = { {A.x, A.y, A.z}, {A.w, Bv.x, Bv.y},
                      {Bv.z, Bv.w, C.x}, {C.y, C.z, C.w} };

    bool anyNb = false, anyS = false, anyA = false;
#pragma unroll
    for (int k = 0; k < 4; ++k) {
        float px = P[k][0], py = P[k][1], pz = P[k][2];
        bool nb = is_nearby(px, py, pz, ax, ay, az);
        int lx = (int)floorf(px / VSC) - v0x;
        int ly = (int)floorf(py / VSC) - v0y;
        int lz = (int)floorf(pz / VSC) - v0z;
        bool bounds = (unsigned)lx < (unsigned)Gq && (unsigned)ly < (unsigned)Gq
                    && (unsigned)lz < (unsigned)Gq;
        int cell = (lx << 12) + (ly << 6) + lz;
        if (bounds) {
            g_occA[(size_t)b * G3q + cell] = 1;
            if (nb) g_occS[(size_t)b * G3q + cell] = 1;
        }
        anyNb |= nb; anyS |= (nb && bounds); anyA |= bounds;
    }
    unsigned mN = __ballot_sync(0xffffffffu, anyNb);
    unsigned mS = __ballot_sync(0xffffffffu, anyS);
    unsigned mA = __ballot_sync(0xffffffffu, anyA);
    if ((threadIdx.x & 31) == 0) {
        if (mN) atomicOr(&g_anyNearby[b], 1);
        if (mS) atomicOr(&g_anyOccS[b], 1);
        if (mA) atomicOr(&g_anyOccA[b], 1);
    }
}

// Precompute chunk-planes: g_P4[(b*16+c4)<<14 | pix] = { sum_c fmap*W1[.,4c4+k] }
__global__ void __launch_bounds__(256) k_proj(const float* __restrict__ fmap,
                                              const float* __restrict__ W1) {
    int idx  = blockIdx.x * 256 + threadIdx.x;   // B*16*NPIX threads
    int pix  = idx & (NPIX - 1);
    int rest = idx >> 14;
    int c4   = rest & 15;
    int b    = rest >> 4;
    const float* fp = fmap + (size_t)b * CF * NPIX + pix;
    int jb = c4 * 4;
    float a0 = 0.f, a1 = 0.f, a2 = 0.f, a3 = 0.f;
#pragma unroll
    for (int c = 0; c < CF; ++c) {
        float v = __ldg(fp + c * NPIX);
        const float* wr = W1 + (3 + c) * 64 + jb;
        a0 = fmaf(v, __ldg(wr + 0), a0);
        a1 = fmaf(v, __ldg(wr + 1), a1);
        a2 = fmaf(v, __ldg(wr + 2), a2);
        a3 = fmaf(v, __ldg(wr + 3), a3);
    }
    g_P4[(size_t)idx] = make_float4(a0, a1, a2, a3);
}

// ---------------------------------------------------------
// Main: thread per voxel (gz fastest -> warp lanes share tap cache lines in
// the chunk-plane layout). Packed f32x2 MLP.
__global__ void __launch_bounds__(256) k_main(const float* __restrict__ pelvis,
                                              const float* __restrict__ Kmat,
                                              const float* __restrict__ bbx,
                                              const float* __restrict__ W1,
                                              const float* __restrict__ b1,
                                              const float* __restrict__ W2,
                                              const float* __restrict__ b2,
                                              float* __restrict__ outp) {
    __shared__ ull  sW1x[32], sW1y[32], sW1z[32], sB1[32];   // packed channel pairs
    __shared__ ull  sW2[64 * 6];                             // row j: 6 packed out-pairs
    __shared__ float sB2[12];
    __shared__ float sred[8][7];

    int t = threadIdx.x;
    if (t < 32) {
        sW1x[t] = pack2(W1[2 * t],       W1[2 * t + 1]);
        sW1y[t] = pack2(W1[64 + 2 * t],  W1[64 + 2 * t + 1]);
        sW1z[t] = pack2(W1[128 + 2 * t], W1[128 + 2 * t + 1]);
        sB1[t]  = pack2(b1[2 * t],       b1[2 * t + 1]);
    }
    if (t >= 64 && t < 64 + 192) {
        int i2 = (t - 64) * 2;
        int j0 = i2 / 6, r0 = i2 % 6;
        sW2[i2]     = pack2(W2[j0 * 12 + 2 * r0], W2[j0 * 12 + 2 * r0 + 1]);
        int i3 = i2 + 1;
        int j1 = i3 / 6, r1 = i3 % 6;
        sW2[i3]     = pack2(W2[j1 * 12 + 2 * r1], W2[j1 * 12 + 2 * r1 + 1]);
    }
    if (t < 12) sB2[t] = b2[t];
    __syncthreads();

    int b = blockIdx.y;
    int g = blockIdx.x * 256 + t;

    float ax = pelvis[b * 3 + 0], ay = pelvis[b * 3 + 1], az = pelvis[b * 3 + 2];
    int anyNb = g_anyNearby[b];
    int v0x = (int)floorf(ax / VSC) - (Gq / 2);
    int v0y = (int)floorf(ay / VSC) - (Gq / 2);
    int v0z = (int)floorf(az / VSC) - (Gq / 2);

    int gx = g >> 12, gy = (g >> 6) & 63, gz = g & 63;
    float cxv = (float)(v0x + gx) * VSC + VSC * 0.5f;
    float cyv = (float)(v0y + gy) * VSC + VSC * 0.5f;
    float czv = (float)(v0z + gz) * VSC + VSC * 0.5f;

    float fx = Kmat[b * 9 + 0], cx0 = Kmat[b * 9 + 2];
    float fy = Kmat[b * 9 + 4], cy0 = Kmat[b * 9 + 5];
    float l = bbx[b * 4 + 0], tp = bbx[b * 4 + 1];
    float r = bbx[b * 4 + 2], bt = bbx[b * 4 + 3];

    float u  = cxv / czv * fx + cx0;
    float vp = cyv / czv * fy + cy0;
    float U = (u - l) / (r - l) * (float)(HW - 1);
    float V = (vp - tp) / (bt - tp) * (float)(HW - 1);

    float x0f = floorf(U), y0f = floorf(V);
    float wx = U - x0f, wy = V - y0f;
    int x0 = (int)x0f, y0 = (int)y0f;
    int x1 = x0 + 1, y1 = y0 + 1;
    bool okx0 = (x0 >= 0 && x0 <= HW - 1), okx1 = (x1 >= 0 && x1 <= HW - 1);
    bool oky0 = (y0 >= 0 && y0 <= HW - 1), oky1 = (y1 >= 0 && y1 <= HW - 1);
    int x0c = min(max(x0, 0), HW - 1), x1c = min(max(x1, 0), HW - 1);
    int y0c = min(max(y0, 0), HW - 1), y1c = min(max(y1, 0), HW - 1);

    float w00 = (1.0f - wx) * (1.0f - wy) * ((okx0 && oky0) ? 1.0f : 0.0f);
    float w10 = wx * (1.0f - wy)          * ((okx1 && oky0) ? 1.0f : 0.0f);
    float w01 = (1.0f - wx) * wy          * ((okx0 && oky1) ? 1.0f : 0.0f);
    float w11 = wx * wy                   * ((okx1 && oky1) ? 1.0f : 0.0f);

    int pix00 = y0c * HW + x0c, pix10 = y0c * HW + x1c;
    int pix01 = y1c * HW + x0c, pix11 = y1c * HW + x1c;

    ull w00_2 = pack2(w00, w00), w10_2 = pack2(w10, w10);
    ull w01_2 = pack2(w01, w01), w11_2 = pack2(w11, w11);
    float geox = ax - cxv, geoy = ay - cyv, geoz = az - czv;
    ull gx2 = pack2(geox, geox), gy2 = pack2(geoy, geoy), gz2 = pack2(geoz, geoz);

    ull acc2[6] = {0ull, 0ull, 0ull, 0ull, 0ull, 0ull};
    const float4* Pbase = g_P4 + ((size_t)(b * 16) << 14);

#pragma unroll
    for (int c = 0; c < 16; ++c) {
        const float4* pl = Pbase + ((size_t)c << 14);
        float4 f00 = __ldg(pl + pix00);
        float4 f10 = __ldg(pl + pix10);
        float4 f01 = __ldg(pl + pix01);
        float4 f11 = __ldg(pl + pix11);
        ulonglong2 t00 = *(ulonglong2*)&f00, t10 = *(ulonglong2*)&f10;
        ulonglong2 t01 = *(ulonglong2*)&f01, t11 = *(ulonglong2*)&f11;

        ull s0 = ffma2(w00_2, t00.x, ffma2(w10_2, t10.x,
                 ffma2(w01_2, t01.x, ffma2(w11_2, t11.x, 0ull))));
        ull s1 = ffma2(w00_2, t00.y, ffma2(w10_2, t10.y,
                 ffma2(w01_2, t01.y, ffma2(w11_2, t11.y, 0ull))));

        int p0 = c * 2;
        ull h0p = ffma2(gx2, sW1x[p0],     ffma2(gy2, sW1y[p0],
                  ffma2(gz2, sW1z[p0],     add2(s0, sB1[p0]))));
        ull h1p = ffma2(gx2, sW1x[p0 + 1], ffma2(gy2, sW1y[p0 + 1],
                  ffma2(gz2, sW1z[p0 + 1], add2(s1, sB1[p0 + 1]))));

        float ha, hb, hc, hd;
        unpack2(h0p, ha, hb); unpack2(h1p, hc, hd);
        ha = fmaxf(ha, 0.0f); hb = fmaxf(hb, 0.0f);
        hc = fmaxf(hc, 0.0f); hd = fmaxf(hd, 0.0f);

        int ch = c * 4;
        const ull* w2a = &sW2[(ch + 0) * 6];
        const ull* w2b = &sW2[(ch + 1) * 6];
        const ull* w2c = &sW2[(ch + 2) * 6];
        const ull* w2d = &sW2[(ch + 3) * 6];
        ull hha = pack2(ha, ha), hhb = pack2(hb, hb);
        ull hhc = pack2(hc, hc), hhd = pack2(hd, hd);
#pragma unroll
        for (int rr = 0; rr < 6; ++rr) {
            acc2[rr] = ffma2(hha, w2a[rr], acc2[rr]);
            acc2[rr] = ffma2(hhb, w2b[rr], acc2[rr]);
            acc2[rr] = ffma2(hhc, w2c[rr], acc2[rr]);
            acc2[rr] = ffma2(hhd, w2d[rr], acc2[rr]);
        }
    }

    float acc[12];
#pragma unroll
    for (int rr = 0; rr < 6; ++rr) {
        unpack2(acc2[rr], acc[2 * rr], acc[2 * rr + 1]);
        acc[2 * rr]     += sB2[2 * rr];
        acc[2 * rr + 1] += sB2[2 * rr + 1];
    }

    // write out[b, g, 0:12]
    float4* op = (float4*)(outp + ((size_t)b * G3q + g) * 12);
    op[0] = make_float4(acc[0], acc[1], acc[2], acc[3]);
    op[1] = make_float4(acc[4], acc[5], acc[6], acc[7]);
    op[2] = make_float4(acc[8], acc[9], acc[10], acc[11]);

    // softmax contributions (shift-free: s = sigmoid in (0,1), exp safe)
    size_t oidx = (size_t)b * G3q + g;
    unsigned char occv = anyNb ? g_occS[oidx] : g_occA[oidx];
    float sg  = 1.0f / (1.0f + expf(-acc[0]));
    float wgt = occv ? expf(sg) : 0.0f;
    float px = cxv + acc[1], py = cyv + acc[2], pz = czv + acc[3];

    float red7[7] = { wgt, wgt * px, wgt * py, wgt * pz, px, py, pz };
#pragma unroll
    for (int i = 0; i < 7; ++i) {
        float vv = red7[i];
        vv += __shfl_xor_sync(0xffffffffu, vv, 16);
        vv += __shfl_xor_sync(0xffffffffu, vv, 8);
        vv += __shfl_xor_sync(0xffffffffu, vv, 4);
        vv += __shfl_xor_sync(0xffffffffu, vv, 2);
        vv += __shfl_xor_sync(0xffffffffu, vv, 1);
        red7[i] = vv;
    }
    int wid = t >> 5, lane = t & 31;
    if (lane == 0) {
#pragma unroll
        for (int i = 0; i < 7; ++i) sred[wid][i] = red7[i];
    }
    __syncthreads();
    if (t < 7) {
        float s = 0.0f;
#pragma unroll
        for (int w = 0; w < 8; ++w) s += sred[w][t];
        atomicAdd(&g_accum[b][t], s);
    }
}

__global__ void k_finalize(const float* __restrict__ pelvis,
                           float* __restrict__ refined) {
    int b = threadIdx.x;
    if (b >= Bq) return;
    int anyOcc = g_anyNearby[b] ? g_anyOccS[b] : g_anyOccA[b];
    float wsum = g_accum[b][0];
    float x, y, z;
    if (anyOcc) {
        x = g_accum[b][1] / wsum;
        y = g_accum[b][2] / wsum;
        z = g_accum[b][3] / wsum;
    } else {
        x = g_accum[b][4] / (float)G3q;
        y = g_accum[b][5] / (float)G3q;
        z = g_accum[b][6] / (float)G3q;
    }
    bool bad = isnan(x) || isnan(y) || isnan(z);
    refined[b * 3 + 0] = bad ? pelvis[b * 3 + 0] : x;
    refined[b * 3 + 1] = bad ? pelvis[b * 3 + 1] : y;
    refined[b * 3 + 2] = bad ? pelvis[b * 3 + 2] : z;
}

extern "C" void kernel_launch(void* const* d_in, const int* in_sizes, int n_in,
                              void* d_out, int out_size) {
    const float* points = (const float*)d_in[0];
    const float* fmap   = (const float*)d_in[1];
    const float* pelvis = (const float*)d_in[2];
    const float* Kmat   = (const float*)d_in[3];
    const float* bbx    = (const float*)d_in[4];
    const float* W1     = (const float*)d_in[5];
    const float* b1     = (const float*)d_in[6];
    const float* W2     = (const float*)d_in[7];
    const float* b2     = (const float*)d_in[8];

    float* refined = (float*)d_out;          // (B,3) first
    float* outp    = (float*)d_out + Bq * 3; // (B,G3,12) second

    k_clear<<<G3q / 256, 256>>>();
    k_proj<<<(Bq * 16 * NPIX) / 256, 256>>>(fmap, W1);
    k_scatter<<<(Bq * Nq / 4) / 256, 256>>>(points, pelvis);
    k_main<<<dim3(G3q / 256, Bq), 256>>>(pelvis, Kmat, bbx, W1, b1, W2, b2, outp);
    k_finalize<<<1, 32>>>(pelvis, refined);
}

// round 7
// speedup vs baseline: 2.2625x; 1.3149x over previous
#include <cuda_runtime.h>
#include <cuda_fp16.h>
#include <math.h>

#define Bq   4
#define Nq   65536
#define Gq   64
#define G3q  262144          // 64^3
#define CF   32
#define HW   128
#define NPIX (HW * HW)       // 16384
#define VSC  0.05f
#define R2C  1.5625f         // 1.25^2

typedef unsigned long long ull;

// -------- device scratch (no allocations allowed) --------
// P stored fp16 as 8 channel-chunk planes per batch:
// g_Ph[((b*8 + c8) << 14) + pix] = uint4 = 8 halves = channels 8*c8 .. 8*c8+7
__device__ uint4         g_Ph[(size_t)Bq * 8 * NPIX];      // 8 MB projected feature map
__device__ unsigned char g_occS[(size_t)Bq * G3q];         // occupancy (nearby-gated)
__device__ unsigned char g_occA[(size_t)Bq * G3q];         // occupancy (bounds only)
__device__ int           g_anyNearby[Bq];
__device__ int           g_anyOccS[Bq];
__device__ int           g_anyOccA[Bq];
__device__ float         g_accum[Bq][8];

// -------- packed f32x2 helpers --------
__device__ __forceinline__ ull ffma2(ull a, ull b, ull c) {
    ull d; asm("fma.rn.f32x2 %0,%1,%2,%3;" : "=l"(d) : "l"(a), "l"(b), "l"(c)); return d;
}
__device__ __forceinline__ ull add2(ull a, ull b) {
    ull d; asm("add.rn.f32x2 %0,%1,%2;" : "=l"(d) : "l"(a), "l"(b)); return d;
}
__device__ __forceinline__ ull pack2(float lo, float hi) {
    ull d; asm("mov.b64 %0,{%1,%2};" : "=l"(d) : "f"(lo), "f"(hi)); return d;
}
__device__ __forceinline__ void unpack2(ull v, float& lo, float& hi) {
    asm("mov.b64 {%0,%1},%2;" : "=f"(lo), "=f"(hi) : "l"(v));
}

// ---------------------------------------------------------
__global__ void k_clear() {
    int i = blockIdx.x * blockDim.x + threadIdx.x;   // 0 .. 262143
    ((int*)g_occS)[i] = 0;
    ((int*)g_occA)[i] = 0;
    if (i < Bq) { g_anyNearby[i] = 0; g_anyOccS[i] = 0; g_anyOccA[i] = 0; }
    if (i < Bq * 8) ((float*)g_accum)[i] = 0.0f;
}

__device__ __forceinline__ bool is_nearby(float px, float py, float pz,
                                          float ax, float ay, float az) {
    float dx = px - ax, dy = py - ay;
    float d2xy = dx * dx + dy * dy;
    float e0 = pz - (az - 0.5f);
    float e1 = pz - az;
    float e2 = pz - (az + 0.5f);
    float m = fminf(fminf(e0 * e0, e1 * e1), e2 * e2);
    return (d2xy + m) <= R2C;
}

// fused scatter: both occupancy grids + flags (4 points/thread)
__global__ void __launch_bounds__(256) k_scatter(const float* __restrict__ points,
                                                 const float* __restrict__ pelvis) {
    int idx4 = blockIdx.x * 256 + threadIdx.x;      // B*N/4 groups
    int b = idx4 >> 14;
    float ax = pelvis[b * 3 + 0], ay = pelvis[b * 3 + 1], az = pelvis[b * 3 + 2];
    int v0x = (int)floorf(ax / VSC) - (Gq / 2);
    int v0y = (int)floorf(ay / VSC) - (Gq / 2);
    int v0z = (int)floorf(az / VSC) - (Gq / 2);

    const float4* pp = (const float4*)(points + (size_t)idx4 * 12);
    float4 A = pp[0], Bv = pp[1], C = pp[2];
    float P[4][3] = { {A.x, A.y, A.z}, {A.w, Bv.x, Bv.y},
                      {Bv.z, Bv.w, C.x}, {C.y, C.z, C.w} };

    bool anyNb = false, anyS = false, anyA = false;
#pragma unroll
    for (int k = 0; k < 4; ++k) {
        float px = P[k][0], py = P[k][1], pz = P[k][2];
        bool nb = is_nearby(px, py, pz, ax, ay, az);
        int lx = (int)floorf(px / VSC) - v0x;
        int ly = (int)floorf(py / VSC) - v0y;
        int lz = (int)floorf(pz / VSC) - v0z;
        bool bounds = (unsigned)lx < (unsigned)Gq && (unsigned)ly < (unsigned)Gq
                    && (unsigned)lz < (unsigned)Gq;
        int cell = (lx << 12) + (ly << 6) + lz;
        if (bounds) {
            g_occA[(size_t)b * G3q + cell] = 1;
            if (nb) g_occS[(size_t)b * G3q + cell] = 1;
        }
        anyNb |= nb; anyS |= (nb && bounds); anyA |= bounds;
    }
    unsigned mN = __ballot_sync(0xffffffffu, anyNb);
    unsigned mS = __ballot_sync(0xffffffffu, anyS);
    unsigned mA = __ballot_sync(0xffffffffu, anyA);
    if ((threadIdx.x & 31) == 0) {
        if (mN) atomicOr(&g_anyNearby[b], 1);
        if (mS) atomicOr(&g_anyOccS[b], 1);
        if (mA) atomicOr(&g_anyOccA[b], 1);
    }
}

// Precompute fp16 chunk-planes: 8 channels per thread (one pixel, one chunk)
__global__ void __launch_bounds__(256) k_proj(const float* __restrict__ fmap,
                                              const float* __restrict__ W1) {
    int idx  = blockIdx.x * 256 + threadIdx.x;   // B*8*NPIX threads
    int pix  = idx & (NPIX - 1);
    int rest = idx >> 14;
    int c8   = rest & 7;
    int b    = rest >> 3;
    const float* fp = fmap + (size_t)b * CF * NPIX + pix;
    int jb = c8 * 8;
    float a0 = 0.f, a1 = 0.f, a2 = 0.f, a3 = 0.f;
    float a4 = 0.f, a5 = 0.f, a6 = 0.f, a7 = 0.f;
#pragma unroll
    for (int c = 0; c < CF; ++c) {
        float v = __ldg(fp + c * NPIX);
        const float* wr = W1 + (3 + c) * 64 + jb;
        a0 = fmaf(v, __ldg(wr + 0), a0);
        a1 = fmaf(v, __ldg(wr + 1), a1);
        a2 = fmaf(v, __ldg(wr + 2), a2);
        a3 = fmaf(v, __ldg(wr + 3), a3);
        a4 = fmaf(v, __ldg(wr + 4), a4);
        a5 = fmaf(v, __ldg(wr + 5), a5);
        a6 = fmaf(v, __ldg(wr + 6), a6);
        a7 = fmaf(v, __ldg(wr + 7), a7);
    }
    __half2 h0 = __floats2half2_rn(a0, a1);
    __half2 h1 = __floats2half2_rn(a2, a3);
    __half2 h2 = __floats2half2_rn(a4, a5);
    __half2 h3 = __floats2half2_rn(a6, a7);
    uint4 o;
    o.x = *(unsigned*)&h0; o.y = *(unsigned*)&h1;
    o.z = *(unsigned*)&h2; o.w = *(unsigned*)&h3;
    g_Ph[(size_t)idx] = o;
}

// ---------------------------------------------------------
// Main: thread per voxel (gz fastest). fp16 taps (8ch per LDG.128) converted
// to fp32, bilinear + MLP in packed f32x2.
__global__ void __launch_bounds__(256) k_main(const float* __restrict__ pelvis,
                                              const float* __restrict__ Kmat,
                                              const float* __restrict__ bbx,
                                              const float* __restrict__ W1,
                                              const float* __restrict__ b1,
                                              const float* __restrict__ W2,
                                              const float* __restrict__ b2,
                                              float* __restrict__ outp) {
    __shared__ ull  sW1x[32], sW1y[32], sW1z[32], sB1[32];   // packed channel pairs
    __shared__ ull  sW2[64 * 6];                             // row j: 6 packed out-pairs
    __shared__ float sB2[12];
    __shared__ float sred[8][7];

    int t = threadIdx.x;
    if (t < 32) {
        sW1x[t] = pack2(W1[2 * t],       W1[2 * t + 1]);
        sW1y[t] = pack2(W1[64 + 2 * t],  W1[64 + 2 * t + 1]);
        sW1z[t] = pack2(W1[128 + 2 * t], W1[128 + 2 * t + 1]);
        sB1[t]  = pack2(b1[2 * t],       b1[2 * t + 1]);
    }
    if (t >= 64 && t < 64 + 192) {
        int i2 = (t - 64) * 2;
        int j0 = i2 / 6, r0 = i2 % 6;
        sW2[i2] = pack2(W2[j0 * 12 + 2 * r0], W2[j0 * 12 + 2 * r0 + 1]);
        int i3 = i2 + 1;
        int j1 = i3 / 6, r1 = i3 % 6;
        sW2[i3] = pack2(W2[j1 * 12 + 2 * r1], W2[j1 * 12 + 2 * r1 + 1]);
    }
    if (t < 12) sB2[t] = b2[t];
    __syncthreads();

    int b = blockIdx.y;
    int g = blockIdx.x * 256 + t;

    float ax = pelvis[b * 3 + 0], ay = pelvis[b * 3 + 1], az = pelvis[b * 3 + 2];
    int anyNb = g_anyNearby[b];
    int v0x = (int)floorf(ax / VSC) - (Gq / 2);
    int v0y = (int)floorf(ay / VSC) - (Gq / 2);
    int v0z = (int)floorf(az / VSC) - (Gq / 2);

    int gx = g >> 12, gy = (g >> 6) & 63, gz = g & 63;
    float cxv = (float)(v0x + gx) * VSC + VSC * 0.5f;
    float cyv = (float)(v0y + gy) * VSC + VSC * 0.5f;
    float czv = (float)(v0z + gz) * VSC + VSC * 0.5f;

    float fx = Kmat[b * 9 + 0], cx0 = Kmat[b * 9 + 2];
    float fy = Kmat[b * 9 + 4], cy0 = Kmat[b * 9 + 5];
    float l = bbx[b * 4 + 0], tp = bbx[b * 4 + 1];
    float r = bbx[b * 4 + 2], bt = bbx[b * 4 + 3];

    float u  = cxv / czv * fx + cx0;
    float vp = cyv / czv * fy + cy0;
    float U = (u - l) / (r - l) * (float)(HW - 1);
    float V = (vp - tp) / (bt - tp) * (float)(HW - 1);

    float x0f = floorf(U), y0f = floorf(V);
    float wx = U - x0f, wy = V - y0f;
    int x0 = (int)x0f, y0 = (int)y0f;
    int x1 = x0 + 1, y1 = y0 + 1;
    bool okx0 = (x0 >= 0 && x0 <= HW - 1), okx1 = (x1 >= 0 && x1 <= HW - 1);
    bool oky0 = (y0 >= 0 && y0 <= HW - 1), oky1 = (y1 >= 0 && y1 <= HW - 1);
    int x0c = min(max(x0, 0), HW - 1), x1c = min(max(x1, 0), HW - 1);
    int y0c = min(max(y0, 0), HW - 1), y1c = min(max(y1, 0), HW - 1);

    float w00 = (1.0f - wx) * (1.0f - wy) * ((okx0 && oky0) ? 1.0f : 0.0f);
    float w10 = wx * (1.0f - wy)          * ((okx1 && oky0) ? 1.0f : 0.0f);
    float w01 = (1.0f - wx) * wy          * ((okx0 && oky1) ? 1.0f : 0.0f);
    float w11 = wx * wy                   * ((okx1 && oky1) ? 1.0f : 0.0f);

    int pix00 = y0c * HW + x0c, pix10 = y0c * HW + x1c;
    int pix01 = y1c * HW + x0c, pix11 = y1c * HW + x1c;

    ull w00_2 = pack2(w00, w00), w10_2 = pack2(w10, w10);
    ull w01_2 = pack2(w01, w01), w11_2 = pack2(w11, w11);
    float geox = ax - cxv, geoy = ay - cyv, geoz = az - czv;
    ull gx2 = pack2(geox, geox), gy2 = pack2(geoy, geoy), gz2 = pack2(geoz, geoz);

    ull acc2[6] = {0ull, 0ull, 0ull, 0ull, 0ull, 0ull};
    const uint4* Pbase = g_Ph + ((size_t)(b * 8) << 14);

#pragma unroll
    for (int c = 0; c < 8; ++c) {
        const uint4* pl = Pbase + ((size_t)c << 14);
        uint4 q00 = __ldg(pl + pix00);
        uint4 q10 = __ldg(pl + pix10);
        uint4 q01 = __ldg(pl + pix01);
        uint4 q11 = __ldg(pl + pix11);
        const __half2* h00 = (const __half2*)&q00;
        const __half2* h10 = (const __half2*)&q10;
        const __half2* h01 = (const __half2*)&q01;
        const __half2* h11 = (const __half2*)&q11;

#pragma unroll
        for (int jj = 0; jj < 4; ++jj) {
            float2 f00 = __half22float2(h00[jj]);
            float2 f10 = __half22float2(h10[jj]);
            float2 f01 = __half22float2(h01[jj]);
            float2 f11 = __half22float2(h11[jj]);
            ull s = ffma2(w00_2, pack2(f00.x, f00.y),
                    ffma2(w10_2, pack2(f10.x, f10.y),
                    ffma2(w01_2, pack2(f01.x, f01.y),
                    ffma2(w11_2, pack2(f11.x, f11.y), 0ull))));

            int p0 = c * 4 + jj;      // packed channel-pair index (0..31)
            ull hp = ffma2(gx2, sW1x[p0], ffma2(gy2, sW1y[p0],
                     ffma2(gz2, sW1z[p0], add2(s, sB1[p0]))));

            float ha, hb;
            unpack2(hp, ha, hb);
            ha = fmaxf(ha, 0.0f); hb = fmaxf(hb, 0.0f);

            int ch = c * 8 + jj * 2;
            const ull* w2a = &sW2[ch * 6];
            const ull* w2b = &sW2[(ch + 1) * 6];
            ull hha = pack2(ha, ha), hhb = pack2(hb, hb);
#pragma unroll
            for (int rr = 0; rr < 6; ++rr) {
                acc2[rr] = ffma2(hha, w2a[rr], ffma2(hhb, w2b[rr], acc2[rr]));
            }
        }
    }

    float acc[12];
#pragma unroll
    for (int rr = 0; rr < 6; ++rr) {
        unpack2(acc2[rr], acc[2 * rr], acc[2 * rr + 1]);
        acc[2 * rr]     += sB2[2 * rr];
        acc[2 * rr + 1] += sB2[2 * rr + 1];
    }

    // write out[b, g, 0:12]
    float4* op = (float4*)(outp + ((size_t)b * G3q + g) * 12);
    op[0] = make_float4(acc[0], acc[1], acc[2], acc[3]);
    op[1] = make_float4(acc[4], acc[5], acc[6], acc[7]);
    op[2] = make_float4(acc[8], acc[9], acc[10], acc[11]);

    // softmax contributions (shift-free: s = sigmoid in (0,1), exp safe)
    size_t oidx = (size_t)b * G3q + g;
    unsigned char occv = anyNb ? g_occS[oidx] : g_occA[oidx];
    float sg  = 1.0f / (1.0f + expf(-acc[0]));
    float wgt = occv ? expf(sg) : 0.0f;
    float px = cxv + acc[1], py = cyv + acc[2], pz = czv + acc[3];

    float red7[7] = { wgt, wgt * px, wgt * py, wgt * pz, px, py, pz };
#pragma unroll
    for (int i = 0; i < 7; ++i) {
        float vv = red7[i];
        vv += __shfl_xor_sync(0xffffffffu, vv, 16);
        vv += __shfl_xor_sync(0xffffffffu, vv, 8);
        vv += __shfl_xor_sync(0xffffffffu, vv, 4);
        vv += __shfl_xor_sync(0xffffffffu, vv, 2);
        vv += __shfl_xor_sync(0xffffffffu, vv, 1);
        red7[i] = vv;
    }
    int wid = t >> 5, lane = t & 31;
    if (lane == 0) {
#pragma unroll
        for (int i = 0; i < 7; ++i) sred[wid][i] = red7[i];
    }
    __syncthreads();
    if (t < 7) {
        float s = 0.0f;
#pragma unroll
        for (int w = 0; w < 8; ++w) s += sred[w][t];
        atomicAdd(&g_accum[b][t], s);
    }
}

__global__ void k_finalize(const float* __restrict__ pelvis,
                           float* __restrict__ refined) {
    int b = threadIdx.x;
    if (b >= Bq) return;
    int anyOcc = g_anyNearby[b] ? g_anyOccS[b] : g_anyOccA[b];
    float wsum = g_accum[b][0];
    float x, y, z;
    if (anyOcc) {
        x = g_accum[b][1] / wsum;
        y = g_accum[b][2] / wsum;
        z = g_accum[b][3] / wsum;
    } else {
        x = g_accum[b][4] / (float)G3q;
        y = g_accum[b][5] / (float)G3q;
        z = g_accum[b][6] / (float)G3q;
    }
    bool bad = isnan(x) || isnan(y) || isnan(z);
    refined[b * 3 + 0] = bad ? pelvis[b * 3 + 0] : x;
    refined[b * 3 + 1] = bad ? pelvis[b * 3 + 1] : y;
    refined[b * 3 + 2] = bad ? pelvis[b * 3 + 2] : z;
}

extern "C" void kernel_launch(void* const* d_in, const int* in_sizes, int n_in,
                              void* d_out, int out_size) {
    const float* points = (const float*)d_in[0];
    const float* fmap   = (const float*)d_in[1];
    const float* pelvis = (const float*)d_in[2];
    const float* Kmat   = (const float*)d_in[3];
    const float* bbx    = (const float*)d_in[4];
    const float* W1     = (const float*)d_in[5];
    const float* b1     = (const float*)d_in[6];
    const float* W2     = (const float*)d_in[7];
    const float* b2     = (const float*)d_in[8];

    float* refined = (float*)d_out;          // (B,3) first
    float* outp    = (float*)d_out + Bq * 3; // (B,G3,12) second

    k_clear<<<G3q / 256, 256>>>();
    k_proj<<<(Bq * 8 * NPIX) / 256, 256>>>(fmap, W1);
    k_scatter<<<(Bq * Nq / 4) / 256, 256>>>(points, pelvis);
    k_main<<<dim3(G3q / 256, Bq), 256>>>(pelvis, Kmat, bbx, W1, b1, W2, b2, outp);
    k_finalize<<<1, 32>>>(pelvis, refined);
}

// round 8
// speedup vs baseline: 2.5323x; 1.1193x over previous
#include <cuda_runtime.h>
#include <cuda_fp16.h>
#include <math.h>

#define Bq   4
#define Nq   65536
#define Gq   64
#define G3q  262144          // 64^3
#define CF   32
#define HW   128
#define NPIX (HW * HW)       // 16384
#define VSC  0.05f
#define R2C  1.5625f         // 1.25^2

typedef unsigned long long ull;

// -------- device scratch (no allocations allowed) --------
// P fp16, 8 channel-chunk planes per batch: g_Ph[((b*8+c8)<<14)+pix] = 8 halves
__device__ uint4         g_Ph[(size_t)Bq * 8 * NPIX];      // 8 MB
__device__ unsigned char g_occS[(size_t)Bq * G3q];
__device__ unsigned char g_occA[(size_t)Bq * G3q];
__device__ int           g_anyNearby[Bq];
__device__ int           g_anyOccS[Bq];
__device__ int           g_anyOccA[Bq];
__device__ float         g_accum[Bq][8];

// -------- packed f32x2 helpers --------
__device__ __forceinline__ ull ffma2(ull a, ull b, ull c) {
    ull d; asm("fma.rn.f32x2 %0,%1,%2,%3;" : "=l"(d) : "l"(a), "l"(b), "l"(c)); return d;
}
__device__ __forceinline__ ull add2(ull a, ull b) {
    ull d; asm("add.rn.f32x2 %0,%1,%2;" : "=l"(d) : "l"(a), "l"(b)); return d;
}
__device__ __forceinline__ ull pack2(float lo, float hi) {
    ull d; asm("mov.b64 %0,{%1,%2};" : "=l"(d) : "f"(lo), "f"(hi)); return d;
}
__device__ __forceinline__ void unpack2(ull v, float& lo, float& hi) {
    asm("mov.b64 {%0,%1},%2;" : "=f"(lo), "=f"(hi) : "l"(v));
}

// ---------------------------------------------------------
__global__ void k_clear() {
    int i = blockIdx.x * blockDim.x + threadIdx.x;   // 0 .. 262143
    ((int*)g_occS)[i] = 0;
    ((int*)g_occA)[i] = 0;
    if (i < Bq) { g_anyNearby[i] = 0; g_anyOccS[i] = 0; g_anyOccA[i] = 0; }
    if (i < Bq * 8) ((float*)g_accum)[i] = 0.0f;
}

__device__ __forceinline__ bool is_nearby(float px, float py, float pz,
                                          float ax, float ay, float az) {
    float dx = px - ax, dy = py - ay;
    float d2xy = dx * dx + dy * dy;
    float e0 = pz - (az - 0.5f);
    float e1 = pz - az;
    float e2 = pz - (az + 0.5f);
    float m = fminf(fminf(e0 * e0, e1 * e1), e2 * e2);
    return (d2xy + m) <= R2C;
}

// fused scatter: both occupancy grids + flags (4 points/thread)
__global__ void __launch_bounds__(256) k_scatter(const float* __restrict__ points,
                                                 const float* __restrict__ pelvis) {
    int idx4 = blockIdx.x * 256 + threadIdx.x;
    int b = idx4 >> 14;
    float ax = pelvis[b * 3 + 0], ay = pelvis[b * 3 + 1], az = pelvis[b * 3 + 2];
    int v0x = (int)floorf(ax / VSC) - (Gq / 2);
    int v0y = (int)floorf(ay / VSC) - (Gq / 2);
    int v0z = (int)floorf(az / VSC) - (Gq / 2);

    const float4* pp = (const float4*)(points + (size_t)idx4 * 12);
    float4 A = pp[0], Bv = pp[1], C = pp[2];
    float P[4][3] = { {A.x, A.y, A.z}, {A.w, Bv.x, Bv.y},
                      {Bv.z, Bv.w, C.x}, {C.y, C.z, C.w} };

    bool anyNb = false, anyS = false, anyA = false;
#pragma unroll
    for (int k = 0; k < 4; ++k) {
        float px = P[k][0], py = P[k][1], pz = P[k][2];
        bool nb = is_nearby(px, py, pz, ax, ay, az);
        int lx = (int)floorf(px / VSC) - v0x;
        int ly = (int)floorf(py / VSC) - v0y;
        int lz = (int)floorf(pz / VSC) - v0z;
        bool bounds = (unsigned)lx < (unsigned)Gq && (unsigned)ly < (unsigned)Gq
                    && (unsigned)lz < (unsigned)Gq;
        int cell = (lx << 12) + (ly << 6) + lz;
        if (bounds) {
            g_occA[(size_t)b * G3q + cell] = 1;
            if (nb) g_occS[(size_t)b * G3q + cell] = 1;
        }
        anyNb |= nb; anyS |= (nb && bounds); anyA |= bounds;
    }
    unsigned mN = __ballot_sync(0xffffffffu, anyNb);
    unsigned mS = __ballot_sync(0xffffffffu, anyS);
    unsigned mA = __ballot_sync(0xffffffffu, anyA);
    if ((threadIdx.x & 31) == 0) {
        if (mN) atomicOr(&g_anyNearby[b], 1);
        if (mS) atomicOr(&g_anyOccS[b], 1);
        if (mA) atomicOr(&g_anyOccA[b], 1);
    }
}

// k_proj: one pixel per thread, all 64 channels packed-f32x2; weights in SMEM.
__global__ void __launch_bounds__(256) k_proj(const float* __restrict__ fmap,
                                              const float* __restrict__ W1) {
    __shared__ ull sW[CF][32];   // sW[c][p] = (W1[3+c, 2p], W1[3+c, 2p+1])
    int t = threadIdx.x;
    for (int i = t; i < CF * 32; i += 256) {
        int c = i >> 5, p = i & 31;
        sW[c][p] = pack2(W1[(3 + c) * 64 + 2 * p], W1[(3 + c) * 64 + 2 * p + 1]);
    }
    __syncthreads();

    int idx = blockIdx.x * 256 + t;          // B*NPIX threads
    int pix = idx & (NPIX - 1);
    int b   = idx >> 14;
    const float* fp = fmap + (size_t)b * CF * NPIX + pix;

    ull acc2[32];
#pragma unroll
    for (int p = 0; p < 32; ++p) acc2[p] = 0ull;

#pragma unroll 4
    for (int c = 0; c < CF; ++c) {
        float v = __ldg(fp + c * NPIX);
        ull v2 = pack2(v, v);
        const ulonglong2* wr = (const ulonglong2*)sW[c];
#pragma unroll
        for (int p2 = 0; p2 < 16; ++p2) {
            ulonglong2 w = wr[p2];
            acc2[2 * p2]     = ffma2(v2, w.x, acc2[2 * p2]);
            acc2[2 * p2 + 1] = ffma2(v2, w.y, acc2[2 * p2 + 1]);
        }
    }

    uint4* outp = g_Ph + (((size_t)b * 8) << 14) + pix;
#pragma unroll
    for (int c8 = 0; c8 < 8; ++c8) {
        float f0, f1, f2, f3, f4, f5, f6, f7;
        unpack2(acc2[c8 * 4 + 0], f0, f1);
        unpack2(acc2[c8 * 4 + 1], f2, f3);
        unpack2(acc2[c8 * 4 + 2], f4, f5);
        unpack2(acc2[c8 * 4 + 3], f6, f7);
        __half2 h0 = __floats2half2_rn(f0, f1);
        __half2 h1 = __floats2half2_rn(f2, f3);
        __half2 h2 = __floats2half2_rn(f4, f5);
        __half2 h3 = __floats2half2_rn(f6, f7);
        uint4 o;
        o.x = *(unsigned*)&h0; o.y = *(unsigned*)&h1;
        o.z = *(unsigned*)&h2; o.w = *(unsigned*)&h3;
        outp[(size_t)c8 << 14] = o;
    }
}

// ---------------------------------------------------------
// Main: 2 voxels per thread (g and g+256: same gx,gz; gy+4) so every weight
// LDS is shared; LDS.128 weight reads; fp16 taps; packed f32x2 MLP.
__global__ void __launch_bounds__(256) k_main(const float* __restrict__ pelvis,
                                              const float* __restrict__ Kmat,
                                              const float* __restrict__ bbx,
                                              const float* __restrict__ W1,
                                              const float* __restrict__ b1,
                                              const float* __restrict__ W2,
                                              const float* __restrict__ b2,
                                              float* __restrict__ outp) {
    __shared__ ulonglong2 sW1xy[32];     // (xpair, ypair) per channel-pair
    __shared__ ulonglong2 sW1zb[32];     // (zpair, b1pair)
    __shared__ ulonglong2 sW2v[64][3];   // row j: 12 floats as 3 x ulonglong2
    __shared__ float sB2[12];
    __shared__ float sred[8][7];

    int t = threadIdx.x;
    if (t < 32) {
        ulonglong2 xy, zb;
        xy.x = pack2(W1[2 * t],       W1[2 * t + 1]);
        xy.y = pack2(W1[64 + 2 * t],  W1[64 + 2 * t + 1]);
        zb.x = pack2(W1[128 + 2 * t], W1[128 + 2 * t + 1]);
        zb.y = pack2(b1[2 * t],       b1[2 * t + 1]);
        sW1xy[t] = xy; sW1zb[t] = zb;
    }
    if (t >= 64 && t < 64 + 192) {
        int i = t - 64;                  // 0..191 = 64 rows x 3 comps
        int j = i / 3, comp = i % 3;
        const float* wr = W2 + j * 12 + comp * 4;
        ulonglong2 w;
        w.x = pack2(wr[0], wr[1]);
        w.y = pack2(wr[2], wr[3]);
        sW2v[j][comp] = w;
    }
    if (t < 12) sB2[t] = b2[t];
    __syncthreads();

    int b  = blockIdx.y;
    int g0 = blockIdx.x * 512 + t;       // voxel A
    int g1 = g0 + 256;                   // voxel B (gy+4)

    float ax = pelvis[b * 3 + 0], ay = pelvis[b * 3 + 1], az = pelvis[b * 3 + 2];
    int anyNb = g_anyNearby[b];
    int v0x = (int)floorf(ax / VSC) - (Gq / 2);
    int v0y = (int)floorf(ay / VSC) - (Gq / 2);
    int v0z = (int)floorf(az / VSC) - (Gq / 2);

    float fx = Kmat[b * 9 + 0], cx0 = Kmat[b * 9 + 2];
    float fy = Kmat[b * 9 + 4], cy0 = Kmat[b * 9 + 5];
    float l = bbx[b * 4 + 0], tp = bbx[b * 4 + 1];
    float r = bbx[b * 4 + 2], bt = bbx[b * 4 + 3];

    // ---- geometry for both voxels ----
    int gx = g0 >> 12, gyA = (g0 >> 6) & 63, gz = g0 & 63;
    int gyB = gyA + 4;
    float cxv  = (float)(v0x + gx)  * VSC + VSC * 0.5f;
    float cyvA = (float)(v0y + gyA) * VSC + VSC * 0.5f;
    float cyvB = (float)(v0y + gyB) * VSC + VSC * 0.5f;
    float czv  = (float)(v0z + gz)  * VSC + VSC * 0.5f;

    float invz = 1.0f / czv;
    float u  = cxv * invz * fx + cx0;
    float U  = (u - l) / (r - l) * (float)(HW - 1);
    float vpA = cyvA * invz * fy + cy0;
    float vpB = cyvB * invz * fy + cy0;
    float VA = (vpA - tp) / (bt - tp) * (float)(HW - 1);
    float VB = (vpB - tp) / (bt - tp) * (float)(HW - 1);

    float x0f = floorf(U);
    float wx = U - x0f;
    int x0 = (int)x0f, x1 = x0 + 1;
    bool okx0 = (x0 >= 0 && x0 <= HW - 1), okx1 = (x1 >= 0 && x1 <= HW - 1);
    int x0c = min(max(x0, 0), HW - 1), x1c = min(max(x1, 0), HW - 1);

    float y0fA = floorf(VA), y0fB = floorf(VB);
    float wyA = VA - y0fA,  wyB = VB - y0fB;
    int y0A = (int)y0fA, y1A = y0A + 1;
    int y0B = (int)y0fB, y1B = y0B + 1;
    bool oky0A = (y0A >= 0 && y0A <= HW - 1), oky1A = (y1A >= 0 && y1A <= HW - 1);
    bool oky0B = (y0B >= 0 && y0B <= HW - 1), oky1B = (y1B >= 0 && y1B <= HW - 1);
    int y0cA = min(max(y0A, 0), HW - 1), y1cA = min(max(y1A, 0), HW - 1);
    int y0cB = min(max(y0B, 0), HW - 1), y1cB = min(max(y1B, 0), HW - 1);

    float w00A = (1.0f - wx) * (1.0f - wyA) * ((okx0 && oky0A) ? 1.0f : 0.0f);
    float w10A = wx * (1.0f - wyA)          * ((okx1 && oky0A) ? 1.0f : 0.0f);
    float w01A = (1.0f - wx) * wyA          * ((okx0 && oky1A) ? 1.0f : 0.0f);
    float w11A = wx * wyA                   * ((okx1 && oky1A) ? 1.0f : 0.0f);
    float w00B = (1.0f - wx) * (1.0f - wyB) * ((okx0 && oky0B) ? 1.0f : 0.0f);
    float w10B = wx * (1.0f - wyB)          * ((okx1 && oky0B) ? 1.0f : 0.0f);
    float w01B = (1.0f - wx) * wyB          * ((okx0 && oky1B) ? 1.0f : 0.0f);
    float w11B = wx * wyB                   * ((okx1 && oky1B) ? 1.0f : 0.0f);

    int pixA00 = y0cA * HW + x0c, pixA10 = y0cA * HW + x1c;
    int pixA01 = y1cA * HW + x0c, pixA11 = y1cA * HW + x1c;
    int pixB00 = y0cB * HW + x0c, pixB10 = y0cB * HW + x1c;
    int pixB01 = y1cB * HW + x0c, pixB11 = y1cB * HW + x1c;

    ull w00A2 = pack2(w00A, w00A), w10A2 = pack2(w10A, w10A);
    ull w01A2 = pack2(w01A, w01A), w11A2 = pack2(w11A, w11A);
    ull w00B2 = pack2(w00B, w00B), w10B2 = pack2(w10B, w10B);
    ull w01B2 = pack2(w01B, w01B), w11B2 = pack2(w11B, w11B);

    float geox = ax - cxv, geoz = az - czv;
    float geoyA = ay - cyvA, geoyB = ay - cyvB;
    ull gx2 = pack2(geox, geox), gz2 = pack2(geoz, geoz);
    ull gy2A = pack2(geoyA, geoyA), gy2B = pack2(geoyB, geoyB);

    ull accA[6] = {0,0,0,0,0,0};
    ull accB[6] = {0,0,0,0,0,0};
    const uint4* Pbase = g_Ph + ((size_t)(b * 8) << 14);

#pragma unroll
    for (int c = 0; c < 8; ++c) {
        const uint4* pl = Pbase + ((size_t)c << 14);
        uint4 qA00 = __ldg(pl + pixA00);
        uint4 qA10 = __ldg(pl + pixA10);
        uint4 qA01 = __ldg(pl + pixA01);
        uint4 qA11 = __ldg(pl + pixA11);
        uint4 qB00 = __ldg(pl + pixB00);
        uint4 qB10 = __ldg(pl + pixB10);
        uint4 qB01 = __ldg(pl + pixB01);
        uint4 qB11 = __ldg(pl + pixB11);
        const __half2* hA00 = (const __half2*)&qA00;
        const __half2* hA10 = (const __half2*)&qA10;
        const __half2* hA01 = (const __half2*)&qA01;
        const __half2* hA11 = (const __half2*)&qA11;
        const __half2* hB00 = (const __half2*)&qB00;
        const __half2* hB10 = (const __half2*)&qB10;
        const __half2* hB01 = (const __half2*)&qB01;
        const __half2* hB11 = (const __half2*)&qB11;

#pragma unroll
        for (int jj = 0; jj < 4; ++jj) {
            int p0 = c * 4 + jj;
            ulonglong2 wxy = sW1xy[p0];
            ulonglong2 wzb = sW1zb[p0];

            // voxel A
            float2 a00 = __half22float2(hA00[jj]);
            float2 a10 = __half22float2(hA10[jj]);
            float2 a01 = __half22float2(hA01[jj]);
            float2 a11 = __half22float2(hA11[jj]);
            ull sA = ffma2(w00A2, pack2(a00.x, a00.y),
                     ffma2(w10A2, pack2(a10.x, a10.y),
                     ffma2(w01A2, pack2(a01.x, a01.y),
                     ffma2(w11A2, pack2(a11.x, a11.y), 0ull))));
            ull hpA = ffma2(gx2, wxy.x, ffma2(gy2A, wxy.y,
                      ffma2(gz2, wzb.x, add2(sA, wzb.y))));
            float haA, hbA; unpack2(hpA, haA, hbA);
            haA = fmaxf(haA, 0.0f); hbA = fmaxf(hbA, 0.0f);
            ull hhaA = pack2(haA, haA), hhbA = pack2(hbA, hbA);

            // voxel B
            float2 b00v = __half22float2(hB00[jj]);
            float2 b10v = __half22float2(hB10[jj]);
            float2 b01v = __half22float2(hB01[jj]);
            float2 b11v = __half22float2(hB11[jj]);
            ull sB = ffma2(w00B2, pack2(b00v.x, b00v.y),
                     ffma2(w10B2, pack2(b10v.x, b10v.y),
                     ffma2(w01B2, pack2(b01v.x, b01v.y),
                     ffma2(w11B2, pack2(b11v.x, b11v.y), 0ull))));
            ull hpB = ffma2(gx2, wxy.x, ffma2(gy2B, wxy.y,
                      ffma2(gz2, wzb.x, add2(sB, wzb.y))));
            float haB, hbB; unpack2(hpB, haB, hbB);
            haB = fmaxf(haB, 0.0f); hbB = fmaxf(hbB, 0.0f);
            ull hhaB = pack2(haB, haB), hhbB = pack2(hbB, hbB);

            // W2 rows ch, ch+1 shared by both voxels
            int ch = p0 * 2;
            ulonglong2 wa0 = sW2v[ch][0], wa1 = sW2v[ch][1], wa2 = sW2v[ch][2];
            ulonglong2 wb0 = sW2v[ch + 1][0], wb1 = sW2v[ch + 1][1], wb2 = sW2v[ch + 1][2];

            accA[0] = ffma2(hhaA, wa0.x, ffma2(hhbA, wb0.x, accA[0]));
            accA[1] = ffma2(hhaA, wa0.y, ffma2(hhbA, wb0.y, accA[1]));
            accA[2] = ffma2(hhaA, wa1.x, ffma2(hhbA, wb1.x, accA[2]));
            accA[3] = ffma2(hhaA, wa1.y, ffma2(hhbA, wb1.y, accA[3]));
            accA[4] = ffma2(hhaA, wa2.x, ffma2(hhbA, wb2.x, accA[4]));
            accA[5] = ffma2(hhaA, wa2.y, ffma2(hhbA, wb2.y, accA[5]));

            accB[0] = ffma2(hhaB, wa0.x, ffma2(hhbB, wb0.x, accB[0]));
            accB[1] = ffma2(hhaB, wa0.y, ffma2(hhbB, wb0.y, accB[1]));
            accB[2] = ffma2(hhaB, wa1.x, ffma2(hhbB, wb1.x, accB[2]));
            accB[3] = ffma2(hhaB, wa1.y, ffma2(hhbB, wb1.y, accB[3]));
            accB[4] = ffma2(hhaB, wa2.x, ffma2(hhbB, wb2.x, accB[4]));
            accB[5] = ffma2(hhaB, wa2.y, ffma2(hhbB, wb2.y, accB[5]));
        }
    }

    float oA[12], oB[12];
#pragma unroll
    for (int rr = 0; rr < 6; ++rr) {
        unpack2(accA[rr], oA[2 * rr], oA[2 * rr + 1]);
        unpack2(accB[rr], oB[2 * rr], oB[2 * rr + 1]);
        oA[2 * rr] += sB2[2 * rr]; oA[2 * rr + 1] += sB2[2 * rr + 1];
        oB[2 * rr] += sB2[2 * rr]; oB[2 * rr + 1] += sB2[2 * rr + 1];
    }

    float4* opA = (float4*)(outp + ((size_t)b * G3q + g0) * 12);
    opA[0] = make_float4(oA[0], oA[1], oA[2], oA[3]);
    opA[1] = make_float4(oA[4], oA[5], oA[6], oA[7]);
    opA[2] = make_float4(oA[8], oA[9], oA[10], oA[11]);
    float4* opB = (float4*)(outp + ((size_t)b * G3q + g1) * 12);
    opB[0] = make_float4(oB[0], oB[1], oB[2], oB[3]);
    opB[1] = make_float4(oB[4], oB[5], oB[6], oB[7]);
    opB[2] = make_float4(oB[8], oB[9], oB[10], oB[11]);

    // softmax contributions for both voxels (shift-free exp of sigmoid)
    unsigned char occA_ = anyNb ? g_occS[(size_t)b * G3q + g0]
                                : g_occA[(size_t)b * G3q + g0];
    unsigned char occB_ = anyNb ? g_occS[(size_t)b * G3q + g1]
                                : g_occA[(size_t)b * G3q + g1];
    float sgA = 1.0f / (1.0f + expf(-oA[0]));
    float sgB = 1.0f / (1.0f + expf(-oB[0]));
    float wgtA = occA_ ? expf(sgA) : 0.0f;
    float wgtB = occB_ ? expf(sgB) : 0.0f;
    float pxA = cxv + oA[1], pyA = cyvA + oA[2], pzA = czv + oA[3];
    float pxB = cxv + oB[1], pyB = cyvB + oB[2], pzB = czv + oB[3];

    float red7[7] = { wgtA + wgtB,
                      wgtA * pxA + wgtB * pxB,
                      wgtA * pyA + wgtB * pyB,
                      wgtA * pzA + wgtB * pzB,
                      pxA + pxB, pyA + pyB, pzA + pzB };
#pragma unroll
    for (int i = 0; i < 7; ++i) {
        float vv = red7[i];
        vv += __shfl_xor_sync(0xffffffffu, vv, 16);
        vv += __shfl_xor_sync(0xffffffffu, vv, 8);
        vv += __shfl_xor_sync(0xffffffffu, vv, 4);
        vv += __shfl_xor_sync(0xffffffffu, vv, 2);
        vv += __shfl_xor_sync(0xffffffffu, vv, 1);
        red7[i] = vv;
    }
    int wid = t >> 5, lane = t & 31;
    if (lane == 0) {
#pragma unroll
        for (int i = 0; i < 7; ++i) sred[wid][i] = red7[i];
    }
    __syncthreads();
    if (t < 7) {
        float s = 0.0f;
#pragma unroll
        for (int w = 0; w < 8; ++w) s += sred[w][t];
        atomicAdd(&g_accum[b][t], s);
    }
}

__global__ void k_finalize(const float* __restrict__ pelvis,
                           float* __restrict__ refined) {
    int b = threadIdx.x;
    if (b >= Bq) return;
    int anyOcc = g_anyNearby[b] ? g_anyOccS[b] : g_anyOccA[b];
    float wsum = g_accum[b][0];
    float x, y, z;
    if (anyOcc) {
        x = g_accum[b][1] / wsum;
        y = g_accum[b][2] / wsum;
        z = g_accum[b][3] / wsum;
    } else {
        x = g_accum[b][4] / (float)G3q;
        y = g_accum[b][5] / (float)G3q;
        z = g_accum[b][6] / (float)G3q;
    }
    bool bad = isnan(x) || isnan(y) || isnan(z);
    refined[b * 3 + 0] = bad ? pelvis[b * 3 + 0] : x;
    refined[b * 3 + 1] = bad ? pelvis[b * 3 + 1] : y;
    refined[b * 3 + 2] = bad ? pelvis[b * 3 + 2] : z;
}

extern "C" void kernel_launch(void* const* d_in, const int* in_sizes, int n_in,
                              void* d_out, int out_size) {
    const float* points = (const float*)d_in[0];
    const float* fmap   = (const float*)d_in[1];
    const float* pelvis = (const float*)d_in[2];
    const float* Kmat   = (const float*)d_in[3];
    const float* bbx    = (const float*)d_in[4];
    const float* W1     = (const float*)d_in[5];
    const float* b1     = (const float*)d_in[6];
    const float* W2     = (const float*)d_in[7];
    const float* b2     = (const float*)d_in[8];

    float* refined = (float*)d_out;          // (B,3) first
    float* outp    = (float*)d_out + Bq * 3; // (B,G3,12) second

    k_clear<<<G3q / 256, 256>>>();
    k_proj<<<(Bq * NPIX) / 256, 256>>>(fmap, W1);
    k_scatter<<<(Bq * Nq / 4) / 256, 256>>>(points, pelvis);
    k_main<<<dim3(G3q / 512, Bq), 256>>>(pelvis, Kmat, bbx, W1, b1, W2, b2, outp);
    k_finalize<<<1, 32>>>(pelvis, refined);
}